// round 14
// baseline (speedup 1.0000x reference)
#include <cuda_runtime.h>

typedef unsigned long long u64;

// Problem dims
#define B_ 2
#define N_ 512
#define T_ 12
#define E_ 128
#define H_ 8
#define D_ 16
#define BHT 192                // B*H*T
#define SLICE 8192             // N*D
#define HEADSZ (BHT*SLICE)
#define MROWS (B_*N_*T_)       // 12288

// Scratch: heads layout [B,H,T,N,D]
// 0:Qf 1:Kf 2:Vf 3:Qs 4:Ks 5:Vs 6:Qfs
__device__ float g_heads[7][HEADSZ];
__device__ float g_ctx[4][HEADSZ];
// Packed weights: [0..5]=proj W, [6]=Wout. Entry (k*64+c) = (W[k,c], W[k,c+64])
__device__ u64 g_Wp[7][8192];

// ---- packed fp32x2 helpers ----
__device__ __forceinline__ u64 pack2(float lo, float hi) {
    u64 r; asm("mov.b64 %0,{%1,%2};" : "=l"(r) : "f"(lo), "f"(hi)); return r;
}
__device__ __forceinline__ void unpack2(u64 v, float& lo, float& hi) {
    asm("mov.b64 {%0,%1},%2;" : "=f"(lo), "=f"(hi) : "l"(v));
}
__device__ __forceinline__ u64 fma2(u64 a, u64 b, u64 c) {
    u64 d; asm("fma.rn.f32x2 %0,%1,%2,%3;" : "=l"(d) : "l"(a), "l"(b), "l"(c)); return d;
}
__device__ __forceinline__ u64 mul2(u64 a, u64 b) {
    u64 d; asm("mul.rn.f32x2 %0,%1,%2;" : "=l"(d) : "l"(a), "l"(b)); return d;
}
__device__ __forceinline__ float ex2(float x) {
    float y; asm("ex2.approx.ftz.f32 %0,%1;" : "=f"(y) : "f"(x)); return y;
}

struct ProjArgs {
    const float* x[6];
    const float* w[6];
    const float* kj;
    const float* vfp;
};
struct PackArgs { const float* w[7]; };

// ---------------------------------------------------------------------------
// Kernel 0: pack 7 weight matrices into u64 (c, c+64) pairs once.
// ---------------------------------------------------------------------------
__global__ __launch_bounds__(512) void pack_kernel(PackArgs pk) {
    const int p = blockIdx.x;
    const float* W = pk.w[p];
    for (int q = threadIdx.x; q < 8192; q += 512) {
        int k = q >> 6, c = q & 63;
        g_Wp[p][q] = pack2(W[k * 128 + c], W[k * 128 + c + 64]);
    }
}

// ---------------------------------------------------------------------------
// Kernel 1: input projections (64-row tiles, grid 192x6, 256 thr).
// ---------------------------------------------------------------------------
__global__ __launch_bounds__(256) void proj_kernel(ProjArgs args) {
    extern __shared__ u64 smw[];     // 8192 u64 = 64KB
    const int p = blockIdx.y;
    const int tile = blockIdx.x;
    const int tid = threadIdx.x;

    {
        const float4* src = (const float4*)g_Wp[p];
        float4* dst = (float4*)smw;
        for (int i = tid; i < 4096; i += 256) dst[i] = __ldg(&src[i]);
    }
    __syncthreads();

    const float* X = args.x[p] + (size_t)tile * 64 * 128;
    const int cg = tid & 15;
    const int rg = tid >> 4;
    const int r0 = rg << 2;

    u64 acc[4][4];
#pragma unroll
    for (int i = 0; i < 4; i++)
#pragma unroll
        for (int j = 0; j < 4; j++) acc[i][j] = 0ull;

    for (int k0 = 0; k0 < 128; k0 += 4) {
        float4 xv[4];
#pragma unroll
        for (int i = 0; i < 4; i++)
            xv[i] = __ldg((const float4*)&X[(r0 + i) * 128 + k0]);
#pragma unroll
        for (int kk = 0; kk < 4; kk++) {
            u64 w4[4];
#pragma unroll
            for (int j = 0; j < 4; j++)
                w4[j] = smw[(k0 + kk) * 64 + cg + 16 * j];
#pragma unroll
            for (int i = 0; i < 4; i++) {
                float xc = (kk == 0) ? xv[i].x : (kk == 1) ? xv[i].y : (kk == 2) ? xv[i].z : xv[i].w;
                u64 xa = pack2(xc, xc);
#pragma unroll
                for (int j = 0; j < 4; j++)
                    acc[i][j] = fma2(xa, w4[j], acc[i][j]);
            }
        }
    }

    const bool isQs = (p == 3);
#pragma unroll
    for (int i = 0; i < 4; i++) {
        int row = tile * 64 + r0 + i;
        int t = row % T_;
        int n = (row / T_) % N_;
        int b = row / (T_ * N_);
        float kj = 0.f, vfpi = 1.f;
        if (isQs) { kj = args.kj[n]; vfpi = args.vfp[n] + 1e-5f; }
#pragma unroll
        for (int j = 0; j < 4; j++) {
            float vlo, vhi; unpack2(acc[i][j], vlo, vhi);
            int h0 = j, h1 = j + 4;
            int idx0 = (((b * H_ + h0) * T_ + t) * N_ + n) * D_ + cg;
            int idx1 = (((b * H_ + h1) * T_ + t) * N_ + n) * D_ + cg;
            g_heads[p][idx0] = vlo;
            g_heads[p][idx1] = vhi;
            if (isQs) {
                g_heads[6][idx0] = kj * (vlo - vlo * vlo / vfpi);
                g_heads[6][idx1] = kj * (vhi - vhi * vhi / vfpi);
            }
        }
    }
}

// ---------------------------------------------------------------------------
// Kernel 2: attention. ONE row per thread, 512 threads, launch_bounds(512,2)
// -> 64-reg budget (live set ~58, no spills), 32 warps/SM. Grid (192,4).
//  - att != 1: maxless fused single pass (bounded scores).
//  - att == 1 (fs): chunked (4) online-max (Qfs unbounded), ~62 regs.
// ---------------------------------------------------------------------------
#define SCALE_LOG2 0.36067376022224085f   // (1/sqrt(16)) * log2(e)

__global__ __launch_bounds__(512, 2) void attn_kernel() {
    extern __shared__ float sm[];
    float* Bs = sm;                  // 512*16 = 32KB
    float* Vs = sm + 8192;           // 512*16 = 32KB

    const int slice = blockIdx.x;    // 0..191
    const int att = blockIdx.y;      // 0..3

    int ai, bi, vi;
    switch (att) {
        case 0:  ai = 0; bi = 1; vi = 2; break;  // ff: Qf,Kf,Vf
        case 1:  ai = 1; bi = 6; vi = 2; break;  // fs: Kf,Qfs,Vf
        case 2:  ai = 4; bi = 0; vi = 5; break;  // sf: Ks,Qf,Vs
        default: ai = 3; bi = 4; vi = 5; break;  // ss: Qs,Ks,Vs
    }

    const float* Ag = g_heads[ai] + slice * SLICE;
    const float* Bg = g_heads[bi] + slice * SLICE;
    const float* Vg = g_heads[vi] + slice * SLICE;
    float* Og = g_ctx[att] + slice * SLICE;

    const int tid = threadIdx.x;
    for (int i = tid; i < 2048; i += 512) {
        ((float4*)Bs)[i] = __ldg(&((const float4*)Bg)[i]);
        ((float4*)Vs)[i] = __ldg(&((const float4*)Vg)[i]);
    }
    __syncthreads();

    // one row per thread
    u64 a[8];
    {
        const u64 sc2 = pack2(SCALE_LOG2, SCALE_LOG2);
        const u64* Ar = (const u64*)(Ag + tid * 16);
#pragma unroll
        for (int j = 0; j < 8; j++) a[j] = mul2(Ar[j], sc2);
    }

    float sum = 0.f;
    u64 acc[8];
#pragma unroll
    for (int j = 0; j < 8; j++) acc[j] = 0ull;

    if (att != 1) {
        // ================= MAXLESS fused single pass =================
#pragma unroll 4
        for (int m = 0; m < 512; m++) {
            const ulonglong2* Br = (const ulonglong2*)&Bs[m * 16];
            ulonglong2 b01 = Br[0], b23 = Br[1], b45 = Br[2], b67 = Br[3];
            u64 s2 = mul2(a[0], b01.x);
            s2 = fma2(a[1], b01.y, s2);
            s2 = fma2(a[2], b23.x, s2);
            s2 = fma2(a[3], b23.y, s2);
            s2 = fma2(a[4], b45.x, s2);
            s2 = fma2(a[5], b45.y, s2);
            s2 = fma2(a[6], b67.x, s2);
            s2 = fma2(a[7], b67.y, s2);
            float lo, hi; unpack2(s2, lo, hi);
            float pe = ex2(lo + hi);           // bounded: no max needed
            sum += pe;
            u64 pp = pack2(pe, pe);
            const ulonglong2* Vr = (const ulonglong2*)&Vs[m * 16];
            ulonglong2 v01 = Vr[0], v23 = Vr[1], v45 = Vr[2], v67 = Vr[3];
            acc[0] = fma2(pp, v01.x, acc[0]);
            acc[1] = fma2(pp, v01.y, acc[1]);
            acc[2] = fma2(pp, v23.x, acc[2]);
            acc[3] = fma2(pp, v23.y, acc[3]);
            acc[4] = fma2(pp, v45.x, acc[4]);
            acc[5] = fma2(pp, v45.y, acc[5]);
            acc[6] = fma2(pp, v67.x, acc[6]);
            acc[7] = fma2(pp, v67.y, acc[7]);
        }
    } else {
        // ====== fs: chunked (4) online-max (Qfs unbounded) ======
        float mx = -3.0e38f;
#pragma unroll 1
        for (int c0 = 0; c0 < 512; c0 += 4) {
            float sc[4];
#pragma unroll
            for (int mm = 0; mm < 4; mm++) {
                const ulonglong2* Br = (const ulonglong2*)&Bs[(c0 + mm) * 16];
                ulonglong2 b01 = Br[0], b23 = Br[1], b45 = Br[2], b67 = Br[3];
                u64 s2 = mul2(a[0], b01.x);
                s2 = fma2(a[1], b01.y, s2);
                s2 = fma2(a[2], b23.x, s2);
                s2 = fma2(a[3], b23.y, s2);
                s2 = fma2(a[4], b45.x, s2);
                s2 = fma2(a[5], b45.y, s2);
                s2 = fma2(a[6], b67.x, s2);
                s2 = fma2(a[7], b67.y, s2);
                float lo, hi; unpack2(s2, lo, hi);
                sc[mm] = lo + hi;
            }
            float cmx = fmaxf(fmaxf(sc[0], sc[1]), fmaxf(sc[2], sc[3]));
            if (__ballot_sync(0xffffffffu, cmx > mx)) {
                float newmx = fmaxf(mx, cmx);
                float corr = ex2(mx - newmx);   // 1.0f when unchanged
                mx = newmx;
                sum *= corr;
                u64 c2 = pack2(corr, corr);
#pragma unroll
                for (int j = 0; j < 8; j++) acc[j] = mul2(acc[j], c2);
            }
#pragma unroll
            for (int mm = 0; mm < 4; mm++) {
                float pe = ex2(sc[mm] - mx);
                sum += pe;
                u64 pp = pack2(pe, pe);
                const ulonglong2* Vr = (const ulonglong2*)&Vs[(c0 + mm) * 16];
                ulonglong2 v01 = Vr[0], v23 = Vr[1], v45 = Vr[2], v67 = Vr[3];
                acc[0] = fma2(pp, v01.x, acc[0]);
                acc[1] = fma2(pp, v01.y, acc[1]);
                acc[2] = fma2(pp, v23.x, acc[2]);
                acc[3] = fma2(pp, v23.y, acc[3]);
                acc[4] = fma2(pp, v45.x, acc[4]);
                acc[5] = fma2(pp, v45.y, acc[5]);
                acc[6] = fma2(pp, v67.x, acc[6]);
                acc[7] = fma2(pp, v67.y, acc[7]);
            }
        }
    }

    float inv = 1.0f / sum;
    u64 i2 = pack2(inv, inv);
    u64* Or = (u64*)(Og + tid * 16);
#pragma unroll
    for (int j = 0; j < 8; j++) Or[j] = mul2(acc[j], i2);
}

// ---------------------------------------------------------------------------
// Kernel 3: output projection (64-row tiles, grid 192x4, 256 thr).
// ---------------------------------------------------------------------------
__global__ __launch_bounds__(256) void outproj_kernel(
    const float* __restrict__ bout, float* __restrict__ out) {
    extern __shared__ u64 smw[];     // 8192 u64 = 64KB
    const int att = blockIdx.y;
    const int tile = blockIdx.x;
    const int tid = threadIdx.x;

    {
        const float4* src = (const float4*)g_Wp[6];
        float4* dst = (float4*)smw;
        for (int i = tid; i < 4096; i += 256) dst[i] = __ldg(&src[i]);
    }
    __syncthreads();

    const float* ctx = g_ctx[att];
    const int cg = tid & 15;
    const int rg = tid >> 4;
    const int r0 = rg << 2;

    int rowbase[4];
#pragma unroll
    for (int i = 0; i < 4; i++) {
        int row = tile * 64 + r0 + i;
        int t = row % T_;
        int n = (row / T_) % N_;
        int b = row / (T_ * N_);
        rowbase[i] = ((b * H_ * T_ + t) * N_ + n) * D_;
    }

    u64 acc[4][4];
#pragma unroll
    for (int i = 0; i < 4; i++)
#pragma unroll
        for (int j = 0; j < 4; j++) acc[i][j] = 0ull;

    for (int k0 = 0; k0 < 128; k0 += 4) {
        const int h = k0 >> 4;
        const int d0 = k0 & 15;
        float4 xv[4];
#pragma unroll
        for (int i = 0; i < 4; i++)
            xv[i] = __ldg((const float4*)&ctx[rowbase[i] + h * (T_ * N_ * D_) + d0]);
#pragma unroll
        for (int kk = 0; kk < 4; kk++) {
            u64 w4[4];
#pragma unroll
            for (int j = 0; j < 4; j++)
                w4[j] = smw[(k0 + kk) * 64 + cg + 16 * j];
#pragma unroll
            for (int i = 0; i < 4; i++) {
                float xc = (kk == 0) ? xv[i].x : (kk == 1) ? xv[i].y : (kk == 2) ? xv[i].z : xv[i].w;
                u64 xa = pack2(xc, xc);
#pragma unroll
                for (int j = 0; j < 4; j++)
                    acc[i][j] = fma2(xa, w4[j], acc[i][j]);
            }
        }
    }

    float blo[4], bhi[4];
#pragma unroll
    for (int j = 0; j < 4; j++) {
        blo[j] = __ldg(&bout[cg + 16 * j]);
        bhi[j] = __ldg(&bout[cg + 16 * j + 64]);
    }

    float* outp = out + (size_t)att * MROWS * E_;
#pragma unroll
    for (int i = 0; i < 4; i++) {
        int row = tile * 64 + r0 + i;
#pragma unroll
        for (int j = 0; j < 4; j++) {
            float vlo, vhi; unpack2(acc[i][j], vlo, vhi);
            outp[row * 128 + cg + 16 * j]      = vlo + blo[j];
            outp[row * 128 + cg + 16 * j + 64] = vhi + bhi[j];
        }
    }
}

// ---------------------------------------------------------------------------
extern "C" void kernel_launch(void* const* d_in, const int* in_sizes, int n_in,
                              void* d_out, int out_size) {
    ProjArgs pa;
    PackArgs pk;
    for (int i = 0; i < 6; i++) {
        pa.x[i] = (const float*)d_in[i];
        pa.w[i] = (const float*)d_in[6 + i];
        pk.w[i] = (const float*)d_in[6 + i];
    }
    pa.kj  = (const float*)d_in[12];
    pa.vfp = (const float*)d_in[13];
    pk.w[6] = (const float*)d_in[14];
    const float* bout = (const float*)d_in[15];
    float* out = (float*)d_out;

    const int smemW = 65536;     // 64KB packed W
    const int smemAttn = 65536;  // 64KB Bs+Vs

    cudaFuncSetAttribute(proj_kernel, cudaFuncAttributeMaxDynamicSharedMemorySize, smemW);
    cudaFuncSetAttribute(attn_kernel, cudaFuncAttributeMaxDynamicSharedMemorySize, smemAttn);
    cudaFuncSetAttribute(outproj_kernel, cudaFuncAttributeMaxDynamicSharedMemorySize, smemW);

    pack_kernel<<<7, 512>>>(pk);
    proj_kernel<<<dim3(192, 6), 256, smemW>>>(pa);
    attn_kernel<<<dim3(192, 4), 512, smemAttn>>>();
    outproj_kernel<<<dim3(192, 4), 256, smemW>>>(bout, out);
}

// round 15
// speedup vs baseline: 1.1569x; 1.1569x over previous
#include <cuda_runtime.h>

typedef unsigned long long u64;

// Problem dims
#define B_ 2
#define N_ 512
#define T_ 12
#define E_ 128
#define H_ 8
#define D_ 16
#define BHT 192                // B*H*T
#define SLICE 8192             // N*D
#define HEADSZ (BHT*SLICE)
#define MROWS (B_*N_*T_)       // 12288

// Scratch: heads layout [B,H,T,N,D]
// 0:Qf 1:Kf 2:Vf 3:Qs 4:Ks 5:Vs 6:Qfs
__device__ float g_heads[7][HEADSZ];
__device__ float g_ctx[4][HEADSZ];
// Packed weights: [0..5]=proj W, [6]=Wout. Entry (k*64+c) = (W[k,c], W[k,c+64])
__device__ u64 g_Wp[7][8192];

// ---- packed fp32x2 helpers ----
__device__ __forceinline__ u64 pack2(float lo, float hi) {
    u64 r; asm("mov.b64 %0,{%1,%2};" : "=l"(r) : "f"(lo), "f"(hi)); return r;
}
__device__ __forceinline__ void unpack2(u64 v, float& lo, float& hi) {
    asm("mov.b64 {%0,%1},%2;" : "=f"(lo), "=f"(hi) : "l"(v));
}
__device__ __forceinline__ u64 fma2(u64 a, u64 b, u64 c) {
    u64 d; asm("fma.rn.f32x2 %0,%1,%2,%3;" : "=l"(d) : "l"(a), "l"(b), "l"(c)); return d;
}
__device__ __forceinline__ u64 mul2(u64 a, u64 b) {
    u64 d; asm("mul.rn.f32x2 %0,%1,%2;" : "=l"(d) : "l"(a), "l"(b)); return d;
}
__device__ __forceinline__ u64 add2(u64 a, u64 b) {
    u64 d; asm("add.rn.f32x2 %0,%1,%2;" : "=l"(d) : "l"(a), "l"(b)); return d;
}
__device__ __forceinline__ float ex2(float x) {
    float y; asm("ex2.approx.ftz.f32 %0,%1;" : "=f"(y) : "f"(x)); return y;
}

struct ProjArgs {
    const float* x[6];
    const float* w[6];
    const float* kj;
    const float* vfp;
};
struct PackArgs { const float* w[7]; };

// ---------------------------------------------------------------------------
// Kernel 0: pack 7 weight matrices into u64 (c, c+64) pairs once.
// ---------------------------------------------------------------------------
__global__ __launch_bounds__(512) void pack_kernel(PackArgs pk) {
    const int p = blockIdx.x;
    const float* W = pk.w[p];
    for (int q = threadIdx.x; q < 8192; q += 512) {
        int k = q >> 6, c = q & 63;
        g_Wp[p][q] = pack2(W[k * 128 + c], W[k * 128 + c + 64]);
    }
}

// ---------------------------------------------------------------------------
// Kernel 1: input projections (64-row tiles, grid 192x6, 256 thr).
// ---------------------------------------------------------------------------
__global__ __launch_bounds__(256) void proj_kernel(ProjArgs args) {
    extern __shared__ u64 smw[];     // 8192 u64 = 64KB
    const int p = blockIdx.y;
    const int tile = blockIdx.x;
    const int tid = threadIdx.x;

    {
        const float4* src = (const float4*)g_Wp[p];
        float4* dst = (float4*)smw;
        for (int i = tid; i < 4096; i += 256) dst[i] = __ldg(&src[i]);
    }
    __syncthreads();

    const float* X = args.x[p] + (size_t)tile * 64 * 128;
    const int cg = tid & 15;
    const int rg = tid >> 4;
    const int r0 = rg << 2;

    u64 acc[4][4];
#pragma unroll
    for (int i = 0; i < 4; i++)
#pragma unroll
        for (int j = 0; j < 4; j++) acc[i][j] = 0ull;

    for (int k0 = 0; k0 < 128; k0 += 4) {
        float4 xv[4];
#pragma unroll
        for (int i = 0; i < 4; i++)
            xv[i] = __ldg((const float4*)&X[(r0 + i) * 128 + k0]);
#pragma unroll
        for (int kk = 0; kk < 4; kk++) {
            u64 w4[4];
#pragma unroll
            for (int j = 0; j < 4; j++)
                w4[j] = smw[(k0 + kk) * 64 + cg + 16 * j];
#pragma unroll
            for (int i = 0; i < 4; i++) {
                float xc = (kk == 0) ? xv[i].x : (kk == 1) ? xv[i].y : (kk == 2) ? xv[i].z : xv[i].w;
                u64 xa = pack2(xc, xc);
#pragma unroll
                for (int j = 0; j < 4; j++)
                    acc[i][j] = fma2(xa, w4[j], acc[i][j]);
            }
        }
    }

    const bool isQs = (p == 3);
#pragma unroll
    for (int i = 0; i < 4; i++) {
        int row = tile * 64 + r0 + i;
        int t = row % T_;
        int n = (row / T_) % N_;
        int b = row / (T_ * N_);
        float kj = 0.f, vfpi = 1.f;
        if (isQs) { kj = args.kj[n]; vfpi = args.vfp[n] + 1e-5f; }
#pragma unroll
        for (int j = 0; j < 4; j++) {
            float vlo, vhi; unpack2(acc[i][j], vlo, vhi);
            int h0 = j, h1 = j + 4;
            int idx0 = (((b * H_ + h0) * T_ + t) * N_ + n) * D_ + cg;
            int idx1 = (((b * H_ + h1) * T_ + t) * N_ + n) * D_ + cg;
            g_heads[p][idx0] = vlo;
            g_heads[p][idx1] = vhi;
            if (isQs) {
                g_heads[6][idx0] = kj * (vlo - vlo * vlo / vfpi);
                g_heads[6][idx1] = kj * (vhi - vhi * vhi / vfpi);
            }
        }
    }
}

// ---------------------------------------------------------------------------
// Kernel 2: attention (R10 config restored: 2 rows/thread, (256,2), one
// launch, maxless/fs branch). NEW: QK dot as TWO depth-4 half-chains + add2
// -> 2x score-phase ILP, shorter critical path to exp.
// ---------------------------------------------------------------------------
#define SCALE_LOG2 0.36067376022224085f   // (1/sqrt(16)) * log2(e)

__global__ __launch_bounds__(256, 2) void attn_kernel() {
    extern __shared__ float sm[];
    float* Bs = sm;                  // 512*16 = 32KB
    float* Vs = sm + 8192;           // 512*16 = 32KB

    const int slice = blockIdx.x;    // 0..191
    const int att = blockIdx.y;      // 0..3

    int ai, bi, vi;
    switch (att) {
        case 0:  ai = 0; bi = 1; vi = 2; break;  // ff: Qf,Kf,Vf
        case 1:  ai = 1; bi = 6; vi = 2; break;  // fs: Kf,Qfs,Vf
        case 2:  ai = 4; bi = 0; vi = 5; break;  // sf: Ks,Qf,Vs
        default: ai = 3; bi = 4; vi = 5; break;  // ss: Qs,Ks,Vs
    }

    const float* Ag = g_heads[ai] + slice * SLICE;
    const float* Bg = g_heads[bi] + slice * SLICE;
    const float* Vg = g_heads[vi] + slice * SLICE;
    float* Og = g_ctx[att] + slice * SLICE;

    const int tid = threadIdx.x;
    for (int i = tid; i < 2048; i += 256) {
        ((float4*)Bs)[i] = __ldg(&((const float4*)Bg)[i]);
        ((float4*)Vs)[i] = __ldg(&((const float4*)Vg)[i]);
    }
    __syncthreads();

    // two rows per thread: tid and tid+256
    u64 a[2][8];
    {
        const u64 sc2 = pack2(SCALE_LOG2, SCALE_LOG2);
        const u64* A0 = (const u64*)(Ag + tid * 16);
        const u64* A1 = (const u64*)(Ag + (tid + 256) * 16);
#pragma unroll
        for (int j = 0; j < 8; j++) {
            a[0][j] = mul2(A0[j], sc2);
            a[1][j] = mul2(A1[j], sc2);
        }
    }

    float sum[2] = {0.f, 0.f};
    u64 acc[2][8];
#pragma unroll
    for (int r = 0; r < 2; r++)
#pragma unroll
        for (int j = 0; j < 8; j++) acc[r][j] = 0ull;

    if (att != 1) {
        // ================= MAXLESS fused single pass =================
#pragma unroll 4
        for (int m = 0; m < 512; m++) {
            const ulonglong2* Br = (const ulonglong2*)&Bs[m * 16];
            ulonglong2 b01 = Br[0], b23 = Br[1], b45 = Br[2], b67 = Br[3];
            float pe[2];
#pragma unroll
            for (int r = 0; r < 2; r++) {
                // two depth-4 half-chains for ILP
                u64 sa = mul2(a[r][0], b01.x);
                u64 sb = mul2(a[r][4], b45.x);
                sa = fma2(a[r][1], b01.y, sa);
                sb = fma2(a[r][5], b45.y, sb);
                sa = fma2(a[r][2], b23.x, sa);
                sb = fma2(a[r][6], b67.x, sb);
                sa = fma2(a[r][3], b23.y, sa);
                sb = fma2(a[r][7], b67.y, sb);
                u64 s2 = add2(sa, sb);
                float lo, hi; unpack2(s2, lo, hi);
                pe[r] = ex2(lo + hi);          // bounded: no max needed
                sum[r] += pe[r];
            }
            const ulonglong2* Vr = (const ulonglong2*)&Vs[m * 16];
            ulonglong2 v01 = Vr[0], v23 = Vr[1], v45 = Vr[2], v67 = Vr[3];
#pragma unroll
            for (int r = 0; r < 2; r++) {
                u64 pp = pack2(pe[r], pe[r]);
                acc[r][0] = fma2(pp, v01.x, acc[r][0]);
                acc[r][1] = fma2(pp, v01.y, acc[r][1]);
                acc[r][2] = fma2(pp, v23.x, acc[r][2]);
                acc[r][3] = fma2(pp, v23.y, acc[r][3]);
                acc[r][4] = fma2(pp, v45.x, acc[r][4]);
                acc[r][5] = fma2(pp, v45.y, acc[r][5]);
                acc[r][6] = fma2(pp, v67.x, acc[r][6]);
                acc[r][7] = fma2(pp, v67.y, acc[r][7]);
            }
        }
    } else {
        // ====== fs: chunked (4) online-max (Qfs unbounded) ======
        float mx[2] = {-3.0e38f, -3.0e38f};
#pragma unroll 1
        for (int c0 = 0; c0 < 512; c0 += 4) {
            float sc[2][4];
#pragma unroll
            for (int mm = 0; mm < 4; mm++) {
                const ulonglong2* Br = (const ulonglong2*)&Bs[(c0 + mm) * 16];
                ulonglong2 b01 = Br[0], b23 = Br[1], b45 = Br[2], b67 = Br[3];
#pragma unroll
                for (int r = 0; r < 2; r++) {
                    u64 sa = mul2(a[r][0], b01.x);
                    u64 sb = mul2(a[r][4], b45.x);
                    sa = fma2(a[r][1], b01.y, sa);
                    sb = fma2(a[r][5], b45.y, sb);
                    sa = fma2(a[r][2], b23.x, sa);
                    sb = fma2(a[r][6], b67.x, sb);
                    sa = fma2(a[r][3], b23.y, sa);
                    sb = fma2(a[r][7], b67.y, sb);
                    u64 s2 = add2(sa, sb);
                    float lo, hi; unpack2(s2, lo, hi);
                    sc[r][mm] = lo + hi;
                }
            }
            float cmx[2];
#pragma unroll
            for (int r = 0; r < 2; r++)
                cmx[r] = fmaxf(fmaxf(sc[r][0], sc[r][1]), fmaxf(sc[r][2], sc[r][3]));
            bool improved = (cmx[0] > mx[0]) || (cmx[1] > mx[1]);
            if (__ballot_sync(0xffffffffu, improved)) {
#pragma unroll
                for (int r = 0; r < 2; r++) {
                    float newmx = fmaxf(mx[r], cmx[r]);
                    float corr = ex2(mx[r] - newmx);
                    mx[r] = newmx;
                    sum[r] *= corr;
                    u64 c2 = pack2(corr, corr);
#pragma unroll
                    for (int j = 0; j < 8; j++) acc[r][j] = mul2(acc[r][j], c2);
                }
            }
#pragma unroll
            for (int mm = 0; mm < 4; mm++) {
                const ulonglong2* Vr = (const ulonglong2*)&Vs[(c0 + mm) * 16];
                ulonglong2 v01 = Vr[0], v23 = Vr[1], v45 = Vr[2], v67 = Vr[3];
#pragma unroll
                for (int r = 0; r < 2; r++) {
                    float pe = ex2(sc[r][mm] - mx[r]);
                    sum[r] += pe;
                    u64 pp = pack2(pe, pe);
                    acc[r][0] = fma2(pp, v01.x, acc[r][0]);
                    acc[r][1] = fma2(pp, v01.y, acc[r][1]);
                    acc[r][2] = fma2(pp, v23.x, acc[r][2]);
                    acc[r][3] = fma2(pp, v23.y, acc[r][3]);
                    acc[r][4] = fma2(pp, v45.x, acc[r][4]);
                    acc[r][5] = fma2(pp, v45.y, acc[r][5]);
                    acc[r][6] = fma2(pp, v67.x, acc[r][6]);
                    acc[r][7] = fma2(pp, v67.y, acc[r][7]);
                }
            }
        }
    }

#pragma unroll
    for (int r = 0; r < 2; r++) {
        float inv = 1.0f / sum[r];
        u64 i2 = pack2(inv, inv);
        u64* Or = (u64*)(Og + (tid + r * 256) * 16);
#pragma unroll
        for (int j = 0; j < 8; j++) Or[j] = mul2(acc[r][j], i2);
    }
}

// ---------------------------------------------------------------------------
// Kernel 3: output projection (64-row tiles, grid 192x4, 256 thr).
// ---------------------------------------------------------------------------
__global__ __launch_bounds__(256) void outproj_kernel(
    const float* __restrict__ bout, float* __restrict__ out) {
    extern __shared__ u64 smw[];     // 8192 u64 = 64KB
    const int att = blockIdx.y;
    const int tile = blockIdx.x;
    const int tid = threadIdx.x;

    {
        const float4* src = (const float4*)g_Wp[6];
        float4* dst = (float4*)smw;
        for (int i = tid; i < 4096; i += 256) dst[i] = __ldg(&src[i]);
    }
    __syncthreads();

    const float* ctx = g_ctx[att];
    const int cg = tid & 15;
    const int rg = tid >> 4;
    const int r0 = rg << 2;

    int rowbase[4];
#pragma unroll
    for (int i = 0; i < 4; i++) {
        int row = tile * 64 + r0 + i;
        int t = row % T_;
        int n = (row / T_) % N_;
        int b = row / (T_ * N_);
        rowbase[i] = ((b * H_ * T_ + t) * N_ + n) * D_;
    }

    u64 acc[4][4];
#pragma unroll
    for (int i = 0; i < 4; i++)
#pragma unroll
        for (int j = 0; j < 4; j++) acc[i][j] = 0ull;

    for (int k0 = 0; k0 < 128; k0 += 4) {
        const int h = k0 >> 4;
        const int d0 = k0 & 15;
        float4 xv[4];
#pragma unroll
        for (int i = 0; i < 4; i++)
            xv[i] = __ldg((const float4*)&ctx[rowbase[i] + h * (T_ * N_ * D_) + d0]);
#pragma unroll
        for (int kk = 0; kk < 4; kk++) {
            u64 w4[4];
#pragma unroll
            for (int j = 0; j < 4; j++)
                w4[j] = smw[(k0 + kk) * 64 + cg + 16 * j];
#pragma unroll
            for (int i = 0; i < 4; i++) {
                float xc = (kk == 0) ? xv[i].x : (kk == 1) ? xv[i].y : (kk == 2) ? xv[i].z : xv[i].w;
                u64 xa = pack2(xc, xc);
#pragma unroll
                for (int j = 0; j < 4; j++)
                    acc[i][j] = fma2(xa, w4[j], acc[i][j]);
            }
        }
    }

    float blo[4], bhi[4];
#pragma unroll
    for (int j = 0; j < 4; j++) {
        blo[j] = __ldg(&bout[cg + 16 * j]);
        bhi[j] = __ldg(&bout[cg + 16 * j + 64]);
    }

    float* outp = out + (size_t)att * MROWS * E_;
#pragma unroll
    for (int i = 0; i < 4; i++) {
        int row = tile * 64 + r0 + i;
#pragma unroll
        for (int j = 0; j < 4; j++) {
            float vlo, vhi; unpack2(acc[i][j], vlo, vhi);
            outp[row * 128 + cg + 16 * j]      = vlo + blo[j];
            outp[row * 128 + cg + 16 * j + 64] = vhi + bhi[j];
        }
    }
}

// ---------------------------------------------------------------------------
extern "C" void kernel_launch(void* const* d_in, const int* in_sizes, int n_in,
                              void* d_out, int out_size) {
    ProjArgs pa;
    PackArgs pk;
    for (int i = 0; i < 6; i++) {
        pa.x[i] = (const float*)d_in[i];
        pa.w[i] = (const float*)d_in[6 + i];
        pk.w[i] = (const float*)d_in[6 + i];
    }
    pa.kj  = (const float*)d_in[12];
    pa.vfp = (const float*)d_in[13];
    pk.w[6] = (const float*)d_in[14];
    const float* bout = (const float*)d_in[15];
    float* out = (float*)d_out;

    const int smemW = 65536;     // 64KB packed W
    const int smemAttn = 65536;  // 64KB Bs+Vs

    cudaFuncSetAttribute(proj_kernel, cudaFuncAttributeMaxDynamicSharedMemorySize, smemW);
    cudaFuncSetAttribute(attn_kernel, cudaFuncAttributeMaxDynamicSharedMemorySize, smemAttn);
    cudaFuncSetAttribute(outproj_kernel, cudaFuncAttributeMaxDynamicSharedMemorySize, smemW);

    pack_kernel<<<7, 512>>>(pk);
    proj_kernel<<<dim3(192, 6), 256, smemW>>>(pa);
    attn_kernel<<<dim3(192, 4), 256, smemAttn>>>();
    outproj_kernel<<<dim3(192, 4), 256, smemW>>>(bout, out);
}

// round 16
// speedup vs baseline: 1.3126x; 1.1346x over previous
#include <cuda_runtime.h>

typedef unsigned long long u64;

// Problem dims
#define B_ 2
#define N_ 512
#define T_ 12
#define E_ 128
#define H_ 8
#define D_ 16
#define BHT 192                // B*H*T
#define SLICE 8192             // N*D
#define HEADSZ (BHT*SLICE)
#define MROWS (B_*N_*T_)       // 12288

// Scratch: heads layout [B,H,T,N,D]
// 0:Qf 1:Kf 2:Vf 3:Qs 4:Ks 5:Vs 6:Qfs
__device__ float g_heads[7][HEADSZ];
__device__ float g_ctx[4][HEADSZ];
// Packed weights: [0..5]=proj W, [6]=Wout. Entry (k*64+c) = (W[k,c], W[k,c+64])
__device__ u64 g_Wp[7][8192];

// ---- packed fp32x2 helpers ----
__device__ __forceinline__ u64 pack2(float lo, float hi) {
    u64 r; asm("mov.b64 %0,{%1,%2};" : "=l"(r) : "f"(lo), "f"(hi)); return r;
}
__device__ __forceinline__ void unpack2(u64 v, float& lo, float& hi) {
    asm("mov.b64 {%0,%1},%2;" : "=f"(lo), "=f"(hi) : "l"(v));
}
__device__ __forceinline__ u64 fma2(u64 a, u64 b, u64 c) {
    u64 d; asm("fma.rn.f32x2 %0,%1,%2,%3;" : "=l"(d) : "l"(a), "l"(b), "l"(c)); return d;
}
__device__ __forceinline__ u64 mul2(u64 a, u64 b) {
    u64 d; asm("mul.rn.f32x2 %0,%1,%2;" : "=l"(d) : "l"(a), "l"(b)); return d;
}
__device__ __forceinline__ float ex2(float x) {
    float y; asm("ex2.approx.ftz.f32 %0,%1;" : "=f"(y) : "f"(x)); return y;
}

struct ProjArgs {
    const float* x[6];
    const float* w[6];
    const float* kj;
    const float* vfp;
};
struct PackArgs { const float* w[7]; };

// ---------------------------------------------------------------------------
// Kernel 0: pack 7 weight matrices into u64 (c, c+64) pairs once.
// ---------------------------------------------------------------------------
__global__ __launch_bounds__(512) void pack_kernel(PackArgs pk) {
    const int p = blockIdx.x;
    const float* W = pk.w[p];
    for (int q = threadIdx.x; q < 8192; q += 512) {
        int k = q >> 6, c = q & 63;
        g_Wp[p][q] = pack2(W[k * 128 + c], W[k * 128 + c + 64]);
    }
}

// ---------------------------------------------------------------------------
// Kernel 1: input projections (64-row tiles, grid 192x6, 256 thr).
// ---------------------------------------------------------------------------
__global__ __launch_bounds__(256) void proj_kernel(ProjArgs args) {
    extern __shared__ u64 smw[];     // 8192 u64 = 64KB
    const int p = blockIdx.y;
    const int tile = blockIdx.x;
    const int tid = threadIdx.x;

    {
        const float4* src = (const float4*)g_Wp[p];
        float4* dst = (float4*)smw;
        for (int i = tid; i < 4096; i += 256) dst[i] = __ldg(&src[i]);
    }
    __syncthreads();

    const float* X = args.x[p] + (size_t)tile * 64 * 128;
    const int cg = tid & 15;
    const int rg = tid >> 4;
    const int r0 = rg << 2;

    u64 acc[4][4];
#pragma unroll
    for (int i = 0; i < 4; i++)
#pragma unroll
        for (int j = 0; j < 4; j++) acc[i][j] = 0ull;

    for (int k0 = 0; k0 < 128; k0 += 4) {
        float4 xv[4];
#pragma unroll
        for (int i = 0; i < 4; i++)
            xv[i] = __ldg((const float4*)&X[(r0 + i) * 128 + k0]);
#pragma unroll
        for (int kk = 0; kk < 4; kk++) {
            u64 w4[4];
#pragma unroll
            for (int j = 0; j < 4; j++)
                w4[j] = smw[(k0 + kk) * 64 + cg + 16 * j];
#pragma unroll
            for (int i = 0; i < 4; i++) {
                float xc = (kk == 0) ? xv[i].x : (kk == 1) ? xv[i].y : (kk == 2) ? xv[i].z : xv[i].w;
                u64 xa = pack2(xc, xc);
#pragma unroll
                for (int j = 0; j < 4; j++)
                    acc[i][j] = fma2(xa, w4[j], acc[i][j]);
            }
        }
    }

    const bool isQs = (p == 3);
#pragma unroll
    for (int i = 0; i < 4; i++) {
        int row = tile * 64 + r0 + i;
        int t = row % T_;
        int n = (row / T_) % N_;
        int b = row / (T_ * N_);
        float kj = 0.f, vfpi = 1.f;
        if (isQs) { kj = args.kj[n]; vfpi = args.vfp[n] + 1e-5f; }
#pragma unroll
        for (int j = 0; j < 4; j++) {
            float vlo, vhi; unpack2(acc[i][j], vlo, vhi);
            int h0 = j, h1 = j + 4;
            int idx0 = (((b * H_ + h0) * T_ + t) * N_ + n) * D_ + cg;
            int idx1 = (((b * H_ + h1) * T_ + t) * N_ + n) * D_ + cg;
            g_heads[p][idx0] = vlo;
            g_heads[p][idx1] = vhi;
            if (isQs) {
                g_heads[6][idx0] = kj * (vlo - vlo * vlo / vfpi);
                g_heads[6][idx1] = kj * (vhi - vhi * vhi / vfpi);
            }
        }
    }
}

// ---------------------------------------------------------------------------
// Kernel 2: attention (measured-best config: 2 rows/thread, (256,2), one
// launch, block-uniform maxless/fs split).
// ---------------------------------------------------------------------------
#define SCALE_LOG2 0.36067376022224085f   // (1/sqrt(16)) * log2(e)

__global__ __launch_bounds__(256, 2) void attn_kernel() {
    extern __shared__ float sm[];
    float* Bs = sm;                  // 512*16 = 32KB
    float* Vs = sm + 8192;           // 512*16 = 32KB

    const int slice = blockIdx.x;    // 0..191
    const int att = blockIdx.y;      // 0..3

    int ai, bi, vi;
    switch (att) {
        case 0:  ai = 0; bi = 1; vi = 2; break;  // ff: Qf,Kf,Vf
        case 1:  ai = 1; bi = 6; vi = 2; break;  // fs: Kf,Qfs,Vf
        case 2:  ai = 4; bi = 0; vi = 5; break;  // sf: Ks,Qf,Vs
        default: ai = 3; bi = 4; vi = 5; break;  // ss: Qs,Ks,Vs
    }

    const float* Ag = g_heads[ai] + slice * SLICE;
    const float* Bg = g_heads[bi] + slice * SLICE;
    const float* Vg = g_heads[vi] + slice * SLICE;
    float* Og = g_ctx[att] + slice * SLICE;

    const int tid = threadIdx.x;
    for (int i = tid; i < 2048; i += 256) {
        ((float4*)Bs)[i] = __ldg(&((const float4*)Bg)[i]);
        ((float4*)Vs)[i] = __ldg(&((const float4*)Vg)[i]);
    }
    __syncthreads();

    // two rows per thread: tid and tid+256
    u64 a[2][8];
    {
        const u64 sc2 = pack2(SCALE_LOG2, SCALE_LOG2);
        const u64* A0 = (const u64*)(Ag + tid * 16);
        const u64* A1 = (const u64*)(Ag + (tid + 256) * 16);
#pragma unroll
        for (int j = 0; j < 8; j++) {
            a[0][j] = mul2(A0[j], sc2);
            a[1][j] = mul2(A1[j], sc2);
        }
    }

    float sum[2] = {0.f, 0.f};
    u64 acc[2][8];
#pragma unroll
    for (int r = 0; r < 2; r++)
#pragma unroll
        for (int j = 0; j < 8; j++) acc[r][j] = 0ull;

    if (att != 1) {
        // ================= MAXLESS fused single pass =================
#pragma unroll 4
        for (int m = 0; m < 512; m++) {
            const ulonglong2* Br = (const ulonglong2*)&Bs[m * 16];
            ulonglong2 b01 = Br[0], b23 = Br[1], b45 = Br[2], b67 = Br[3];
            float pe[2];
#pragma unroll
            for (int r = 0; r < 2; r++) {
                u64 s2 = mul2(a[r][0], b01.x);
                s2 = fma2(a[r][1], b01.y, s2);
                s2 = fma2(a[r][2], b23.x, s2);
                s2 = fma2(a[r][3], b23.y, s2);
                s2 = fma2(a[r][4], b45.x, s2);
                s2 = fma2(a[r][5], b45.y, s2);
                s2 = fma2(a[r][6], b67.x, s2);
                s2 = fma2(a[r][7], b67.y, s2);
                float lo, hi; unpack2(s2, lo, hi);
                pe[r] = ex2(lo + hi);          // bounded: no max needed
                sum[r] += pe[r];
            }
            const ulonglong2* Vr = (const ulonglong2*)&Vs[m * 16];
            ulonglong2 v01 = Vr[0], v23 = Vr[1], v45 = Vr[2], v67 = Vr[3];
#pragma unroll
            for (int r = 0; r < 2; r++) {
                u64 pp = pack2(pe[r], pe[r]);
                acc[r][0] = fma2(pp, v01.x, acc[r][0]);
                acc[r][1] = fma2(pp, v01.y, acc[r][1]);
                acc[r][2] = fma2(pp, v23.x, acc[r][2]);
                acc[r][3] = fma2(pp, v23.y, acc[r][3]);
                acc[r][4] = fma2(pp, v45.x, acc[r][4]);
                acc[r][5] = fma2(pp, v45.y, acc[r][5]);
                acc[r][6] = fma2(pp, v67.x, acc[r][6]);
                acc[r][7] = fma2(pp, v67.y, acc[r][7]);
            }
        }
    } else {
        // ====== fs: chunked (4) online-max, lean register footprint ======
        float mx[2] = {-3.0e38f, -3.0e38f};
#pragma unroll 1
        for (int c0 = 0; c0 < 512; c0 += 4) {
            float sc[2][4];
#pragma unroll
            for (int mm = 0; mm < 4; mm++) {
                const ulonglong2* Br = (const ulonglong2*)&Bs[(c0 + mm) * 16];
                ulonglong2 b01 = Br[0], b23 = Br[1], b45 = Br[2], b67 = Br[3];
#pragma unroll
                for (int r = 0; r < 2; r++) {
                    u64 s2 = mul2(a[r][0], b01.x);
                    s2 = fma2(a[r][1], b01.y, s2);
                    s2 = fma2(a[r][2], b23.x, s2);
                    s2 = fma2(a[r][3], b23.y, s2);
                    s2 = fma2(a[r][4], b45.x, s2);
                    s2 = fma2(a[r][5], b45.y, s2);
                    s2 = fma2(a[r][6], b67.x, s2);
                    s2 = fma2(a[r][7], b67.y, s2);
                    float lo, hi; unpack2(s2, lo, hi);
                    sc[r][mm] = lo + hi;
                }
            }
            float cmx[2];
#pragma unroll
            for (int r = 0; r < 2; r++)
                cmx[r] = fmaxf(fmaxf(sc[r][0], sc[r][1]), fmaxf(sc[r][2], sc[r][3]));
            bool improved = (cmx[0] > mx[0]) || (cmx[1] > mx[1]);
            if (__ballot_sync(0xffffffffu, improved)) {
#pragma unroll
                for (int r = 0; r < 2; r++) {
                    float newmx = fmaxf(mx[r], cmx[r]);
                    float corr = ex2(mx[r] - newmx);
                    mx[r] = newmx;
                    sum[r] *= corr;
                    u64 c2 = pack2(corr, corr);
#pragma unroll
                    for (int j = 0; j < 8; j++) acc[r][j] = mul2(acc[r][j], c2);
                }
            }
#pragma unroll
            for (int mm = 0; mm < 4; mm++) {
                const ulonglong2* Vr = (const ulonglong2*)&Vs[(c0 + mm) * 16];
                ulonglong2 v01 = Vr[0], v23 = Vr[1], v45 = Vr[2], v67 = Vr[3];
#pragma unroll
                for (int r = 0; r < 2; r++) {
                    float pe = ex2(sc[r][mm] - mx[r]);
                    sum[r] += pe;
                    u64 pp = pack2(pe, pe);
                    acc[r][0] = fma2(pp, v01.x, acc[r][0]);
                    acc[r][1] = fma2(pp, v01.y, acc[r][1]);
                    acc[r][2] = fma2(pp, v23.x, acc[r][2]);
                    acc[r][3] = fma2(pp, v23.y, acc[r][3]);
                    acc[r][4] = fma2(pp, v45.x, acc[r][4]);
                    acc[r][5] = fma2(pp, v45.y, acc[r][5]);
                    acc[r][6] = fma2(pp, v67.x, acc[r][6]);
                    acc[r][7] = fma2(pp, v67.y, acc[r][7]);
                }
            }
        }
    }

#pragma unroll
    for (int r = 0; r < 2; r++) {
        float inv = 1.0f / sum[r];
        u64 i2 = pack2(inv, inv);
        u64* Or = (u64*)(Og + (tid + r * 256) * 16);
#pragma unroll
        for (int j = 0; j < 8; j++) Or[j] = mul2(acc[r][j], i2);
    }
}

// ---------------------------------------------------------------------------
// Kernel 3: output projection (64-row tiles, grid 192x4, 256 thr).
// ---------------------------------------------------------------------------
__global__ __launch_bounds__(256) void outproj_kernel(
    const float* __restrict__ bout, float* __restrict__ out) {
    extern __shared__ u64 smw[];     // 8192 u64 = 64KB
    const int att = blockIdx.y;
    const int tile = blockIdx.x;
    const int tid = threadIdx.x;

    {
        const float4* src = (const float4*)g_Wp[6];
        float4* dst = (float4*)smw;
        for (int i = tid; i < 4096; i += 256) dst[i] = __ldg(&src[i]);
    }
    __syncthreads();

    const float* ctx = g_ctx[att];
    const int cg = tid & 15;
    const int rg = tid >> 4;
    const int r0 = rg << 2;

    int rowbase[4];
#pragma unroll
    for (int i = 0; i < 4; i++) {
        int row = tile * 64 + r0 + i;
        int t = row % T_;
        int n = (row / T_) % N_;
        int b = row / (T_ * N_);
        rowbase[i] = ((b * H_ * T_ + t) * N_ + n) * D_;
    }

    u64 acc[4][4];
#pragma unroll
    for (int i = 0; i < 4; i++)
#pragma unroll
        for (int j = 0; j < 4; j++) acc[i][j] = 0ull;

    for (int k0 = 0; k0 < 128; k0 += 4) {
        const int h = k0 >> 4;
        const int d0 = k0 & 15;
        float4 xv[4];
#pragma unroll
        for (int i = 0; i < 4; i++)
            xv[i] = __ldg((const float4*)&ctx[rowbase[i] + h * (T_ * N_ * D_) + d0]);
#pragma unroll
        for (int kk = 0; kk < 4; kk++) {
            u64 w4[4];
#pragma unroll
            for (int j = 0; j < 4; j++)
                w4[j] = smw[(k0 + kk) * 64 + cg + 16 * j];
#pragma unroll
            for (int i = 0; i < 4; i++) {
                float xc = (kk == 0) ? xv[i].x : (kk == 1) ? xv[i].y : (kk == 2) ? xv[i].z : xv[i].w;
                u64 xa = pack2(xc, xc);
#pragma unroll
                for (int j = 0; j < 4; j++)
                    acc[i][j] = fma2(xa, w4[j], acc[i][j]);
            }
        }
    }

    float blo[4], bhi[4];
#pragma unroll
    for (int j = 0; j < 4; j++) {
        blo[j] = __ldg(&bout[cg + 16 * j]);
        bhi[j] = __ldg(&bout[cg + 16 * j + 64]);
    }

    float* outp = out + (size_t)att * MROWS * E_;
#pragma unroll
    for (int i = 0; i < 4; i++) {
        int row = tile * 64 + r0 + i;
#pragma unroll
        for (int j = 0; j < 4; j++) {
            float vlo, vhi; unpack2(acc[i][j], vlo, vhi);
            outp[row * 128 + cg + 16 * j]      = vlo + blo[j];
            outp[row * 128 + cg + 16 * j + 64] = vhi + bhi[j];
        }
    }
}

// ---------------------------------------------------------------------------
extern "C" void kernel_launch(void* const* d_in, const int* in_sizes, int n_in,
                              void* d_out, int out_size) {
    ProjArgs pa;
    PackArgs pk;
    for (int i = 0; i < 6; i++) {
        pa.x[i] = (const float*)d_in[i];
        pa.w[i] = (const float*)d_in[6 + i];
        pk.w[i] = (const float*)d_in[6 + i];
    }
    pa.kj  = (const float*)d_in[12];
    pa.vfp = (const float*)d_in[13];
    pk.w[6] = (const float*)d_in[14];
    const float* bout = (const float*)d_in[15];
    float* out = (float*)d_out;

    const int smemW = 65536;     // 64KB packed W
    const int smemAttn = 65536;  // 64KB Bs+Vs

    cudaFuncSetAttribute(proj_kernel, cudaFuncAttributeMaxDynamicSharedMemorySize, smemW);
    cudaFuncSetAttribute(attn_kernel, cudaFuncAttributeMaxDynamicSharedMemorySize, smemAttn);
    cudaFuncSetAttribute(outproj_kernel, cudaFuncAttributeMaxDynamicSharedMemorySize, smemW);

    pack_kernel<<<7, 512>>>(pk);
    proj_kernel<<<dim3(192, 6), 256, smemW>>>(pa);
    attn_kernel<<<dim3(192, 4), 256, smemAttn>>>();
    outproj_kernel<<<dim3(192, 4), 256, smemW>>>(bout, out);
}